// round 4
// baseline (speedup 1.0000x reference)
#include <cuda_runtime.h>
#include <cuda_bf16.h>

#define Nn 50000
#define Ee 800000
#define Hh 128

// ---------------- scratch (device globals; NEVER passed as kernel args) ----
__device__ float g_norm[Nn];
__device__ float g_ew[Ee];
__device__ float g_deg[Nn];
__device__ float g_dinv[Nn];
__device__ float g_xt[(size_t)Nn * Hh];   // lin output of current layer
__device__ float g_agg[(size_t)Nn * Hh];  // scatter accumulator
__device__ float g_h1[(size_t)Nn * Hh];   // hidden after layer 1
__device__ int   g_not_i64;               // 1 if edge_index is int32

// index load honoring runtime-detected dtype (int64 little-endian: low word)
__device__ __forceinline__ int ld_idx(const int* __restrict__ p, int i, int is64) {
    return is64 ? p[2 * i] : p[i];
}

// ---------------- dtype detection ----------------
__global__ void k_reset_flag() { g_not_i64 = 0; }
__global__ void k_detect(const int* __restrict__ ei) {
    int e = blockIdx.x * blockDim.x + threadIdx.x;
    if (e >= Ee) return;
    if (ei[2 * e + 1] != 0) atomicOr(&g_not_i64, 1);
}

// ---------------- zero kernels ----------------
__global__ void k_zero_deg() {
    int i = blockIdx.x * blockDim.x + threadIdx.x;
    if (i < Nn) g_deg[i] = 0.f;
}
__global__ void k_zero_agg() {
    int i = blockIdx.x * blockDim.x + threadIdx.x;
    if (i < Nn * Hh) g_agg[i] = 0.f;
}

// ---------------- node norms: one warp per node ----------------
__global__ void k_norm(const float* __restrict__ x) {
    int node = (blockIdx.x * blockDim.x + threadIdx.x) >> 5;
    int lane = threadIdx.x & 31;
    if (node >= Nn) return;
    float4 v = ((const float4*)(x + (size_t)node * Hh))[lane];
    float ss = v.x * v.x + v.y * v.y + v.z * v.z + v.w * v.w;
    #pragma unroll
    for (int o = 16; o; o >>= 1) ss += __shfl_xor_sync(0xffffffffu, ss, o);
    if (lane == 0) g_norm[node] = fmaxf(sqrtf(ss), 1e-8f);
}

// ---------------- edge weights + degree: one warp per edge ----------------
__global__ void k_edge(const float* __restrict__ x,
                       const int* __restrict__ ei,
                       const int* __restrict__ sat) {
    int e = (blockIdx.x * blockDim.x + threadIdx.x) >> 5;
    int lane = threadIdx.x & 31;
    if (e >= Ee) return;
    int is64 = (g_not_i64 == 0);
    unsigned s = (unsigned)ld_idx(ei, e, is64);
    unsigned d = (unsigned)ld_idx(ei, Ee + e, is64);
    if (s >= Nn || d >= Nn) return;   // never fault
    float4 a = ((const float4*)(x + (size_t)s * Hh))[lane];
    float4 b = ((const float4*)(x + (size_t)d * Hh))[lane];
    float dot = a.x * b.x + a.y * b.y + a.z * b.z + a.w * b.w;
    #pragma unroll
    for (int o = 16; o; o >>= 1) dot += __shfl_xor_sync(0xffffffffu, dot, o);
    if (lane == 0) {
        float sim = dot / (g_norm[s] * g_norm[d]);
        int ss_ = ld_idx(sat, (int)s, is64);
        int sd_ = ld_idx(sat, (int)d, is64);
        float f = (ss_ != sd_) ? 0.36787944117144233f : 1.0f;  // exp(-1)
        float ew = fmaxf(sim * f, 1e-4f);
        g_ew[e] = ew;
        atomicAdd(&g_deg[d], ew);
    }
}

// ---------------- dinv = (deg + 1)^-0.5 ----------------
__global__ void k_dinv() {
    int i = blockIdx.x * blockDim.x + threadIdx.x;
    if (i < Nn) g_dinv[i] = rsqrtf(g_deg[i] + 1.0f);
}

// ---------------- GEMM: g_xt = A @ W ;  A = x param (layer 0) or g_h1 ------
__global__ __launch_bounds__(256) void k_gemm128(const float* __restrict__ Aext,
                                                 const float* __restrict__ W,
                                                 int use_h1) {
    __shared__ float Xs[64][33];
    __shared__ __align__(16) float Ws[32][128];
    const float* __restrict__ A = use_h1 ? (const float*)g_h1 : Aext;
    int tid = threadIdx.x;
    int tx = tid & 15;
    int rt = tid >> 4;
    int row0 = blockIdx.x * 64;

    float acc[4][8];
    #pragma unroll
    for (int i = 0; i < 4; i++)
        #pragma unroll
        for (int j = 0; j < 8; j++) acc[i][j] = 0.f;

    for (int kc = 0; kc < 4; kc++) {
        #pragma unroll
        for (int i = 0; i < 8; i++) {           // 64*32 floats
            int idx = tid + i * 256;
            int r = idx >> 5, k = idx & 31;
            int gr = row0 + r;
            Xs[r][k] = (gr < Nn) ? A[(size_t)gr * 128 + kc * 32 + k] : 0.f;
        }
        #pragma unroll
        for (int i = 0; i < 16; i++) {          // 32*128 floats
            int idx = tid + i * 256;
            int k = idx >> 7, c = idx & 127;
            Ws[k][c] = W[(size_t)(kc * 32 + k) * 128 + c];
        }
        __syncthreads();
        #pragma unroll
        for (int k = 0; k < 32; k++) {
            float4 w0 = *(const float4*)&Ws[k][tx * 8];
            float4 w1 = *(const float4*)&Ws[k][tx * 8 + 4];
            #pragma unroll
            for (int i = 0; i < 4; i++) {
                float xv = Xs[rt * 4 + i][k];
                acc[i][0] += xv * w0.x; acc[i][1] += xv * w0.y;
                acc[i][2] += xv * w0.z; acc[i][3] += xv * w0.w;
                acc[i][4] += xv * w1.x; acc[i][5] += xv * w1.y;
                acc[i][6] += xv * w1.z; acc[i][7] += xv * w1.w;
            }
        }
        __syncthreads();
    }
    #pragma unroll
    for (int i = 0; i < 4; i++) {
        int gr = row0 + rt * 4 + i;
        if (gr < Nn) {
            float4* cp = (float4*)(g_xt + (size_t)gr * 128 + tx * 8);
            cp[0] = make_float4(acc[i][0], acc[i][1], acc[i][2], acc[i][3]);
            cp[1] = make_float4(acc[i][4], acc[i][5], acc[i][6], acc[i][7]);
        }
    }
}

// ---------------- scatter aggregation: one warp per edge -------------------
__global__ void k_agg(const int* __restrict__ ei) {
    int e = (blockIdx.x * blockDim.x + threadIdx.x) >> 5;
    int lane = threadIdx.x & 31;
    if (e >= Ee) return;
    int is64 = (g_not_i64 == 0);
    unsigned s = (unsigned)ld_idx(ei, e, is64);
    unsigned d = (unsigned)ld_idx(ei, Ee + e, is64);
    if (s >= Nn || d >= Nn) return;
    float nrm = g_dinv[s] * g_ew[e] * g_dinv[d];
    float4 v = ((const float4*)(g_xt + (size_t)s * Hh))[lane];
    float* dstp = g_agg + (size_t)d * Hh + lane * 4;
    atomicAdd(dstp + 0, v.x * nrm);
    atomicAdd(dstp + 1, v.y * nrm);
    atomicAdd(dstp + 2, v.z * nrm);
    atomicAdd(dstp + 3, v.w * nrm);
}

// ------ combine: dst = relu(agg + xt*dinv^2 + b); dst = g_h1 or out param --
__global__ void k_combine(const float* __restrict__ b, float* __restrict__ outext,
                          int to_h1) {
    int idx = blockIdx.x * blockDim.x + threadIdx.x;
    if (idx >= Nn * Hh) return;
    int i = idx >> 7, j = idx & 127;
    float di = g_dinv[i];
    float v = g_agg[idx] + g_xt[idx] * di * di + b[j];
    float r = fmaxf(v, 0.f);
    if (to_h1) g_h1[idx] = r; else outext[idx] = r;
}

// ---------------- head: y = h @ Wc + bc, warp per node ---------------------
__global__ void k_y(const float* __restrict__ h, const float* __restrict__ Wc,
                    const float* __restrict__ bc, float* __restrict__ y) {
    int node = (blockIdx.x * blockDim.x + threadIdx.x) >> 5;
    int lane = threadIdx.x & 31;
    if (node >= Nn) return;
    float4 hv = ((const float4*)(h + (size_t)node * Hh))[lane];
    float4 wv = ((const float4*)Wc)[lane];
    float dot = hv.x * wv.x + hv.y * wv.y + hv.z * wv.z + hv.w * wv.w;
    #pragma unroll
    for (int o = 16; o; o >>= 1) dot += __shfl_xor_sync(0xffffffffu, dot, o);
    if (lane == 0) y[node] = dot + bc[0];
}

// ---------------- launch ----------------
extern "C" void kernel_launch(void* const* d_in, const int* in_sizes, int n_in,
                              void* d_out, int out_size) {
    // runtime input-ordering via size fingerprint
    int ix = 0, iei = 1, isa = 2, iW1 = 3, ib1 = 4, iW2 = 5, ib2 = 6, iWc = 7, ibc = 8;
    if (n_in >= 9 && in_sizes[0] != 6400000) {
        if (in_sizes[0] == 16384 && in_sizes[1] == 16384) {
            // alphabetical: W1 W2 Wc b1 b2 bc edge_index sensitive_attr x
            iW1 = 0; iW2 = 1; iWc = 2; ib1 = 3; ib2 = 4; ibc = 5; iei = 6; isa = 7; ix = 8;
        } else {
            int c128a = -1, c128b = -1, c128c = -1, w16a = -1, w16b = -1;
            for (int i = 0; i < n_in; i++) {
                int s = in_sizes[i];
                if (s == 6400000) ix = i;
                else if (s == 1600000 || s == 3200000) iei = i;
                else if (s == 50000 || s == 100000) isa = i;
                else if (s == 16384) { if (w16a < 0) w16a = i; else w16b = i; }
                else if (s == 128) { if (c128a < 0) c128a = i; else if (c128b < 0) c128b = i; else c128c = i; }
                else if (s == 1) ibc = i;
            }
            iW1 = w16a; iW2 = w16b; ib1 = c128a; ib2 = c128b; iWc = c128c;
        }
    }

    const float* x  = (const float*)d_in[ix];
    const int*   ei = (const int*)d_in[iei];
    const int*   sa = (const int*)d_in[isa];
    const float* W1 = (const float*)d_in[iW1];
    const float* b1 = (const float*)d_in[ib1];
    const float* W2 = (const float*)d_in[iW2];
    const float* b2 = (const float*)d_in[ib2];
    const float* Wc = (const float*)d_in[iWc];
    const float* bc = (const float*)d_in[ibc];

    float* out  = (float*)d_out;
    float* yout = out;        // [N]
    float* hout = out + Nn;   // [N, 128]

    const int T = 256;
    const int gN      = (Nn + T - 1) / T;
    const int gNwarp  = (Nn + 7) / 8;
    const int gEwarp  = (Ee + 7) / 8;
    const int gE      = (Ee + T - 1) / T;
    const int gNH     = (Nn * Hh) / T;
    const int gGemm   = (Nn + 63) / 64;

    // dtype detection (int32 vs int64 edge_index)
    k_reset_flag<<<1, 1>>>();
    k_detect<<<gE, T>>>(ei);

    // edge weights + degrees
    k_zero_deg<<<gN, T>>>();
    k_norm<<<gNwarp, T>>>(x);
    k_edge<<<gEwarp, T>>>(x, ei, sa);
    k_dinv<<<gN, T>>>();

    // layer 1: xt = x @ W1 ; agg ; h1 = relu(...)
    k_gemm128<<<gGemm, T>>>(x, W1, 0);
    k_zero_agg<<<gNH, T>>>();
    k_agg<<<gEwarp, T>>>(ei);
    k_combine<<<gNH, T>>>(b1, nullptr, 1);

    // layer 2: xt = h1 @ W2 ; agg ; hout = relu(...)
    k_gemm128<<<gGemm, T>>>(x /*unused*/, W2, 1);
    k_zero_agg<<<gNH, T>>>();
    k_agg<<<gEwarp, T>>>(ei);
    k_combine<<<gNH, T>>>(b2, hout, 0);

    // head
    k_y<<<gNwarp, T>>>(hout, Wc, bc, yout);
}

// round 5
// speedup vs baseline: 1.7493x; 1.7493x over previous
#include <cuda_runtime.h>
#include <cuda_bf16.h>

#define Nn 50000
#define Ee 800000
#define Hh 128

// ---------------- scratch (device globals; NEVER passed as kernel args) ----
__device__ float g_norm[Nn];
__device__ float g_ew[Ee];
__device__ float g_deg[Nn];
__device__ float g_dinv[Nn];
__device__ float g_xt[(size_t)Nn * Hh];     // lin output of current layer
__device__ float g_h1[(size_t)Nn * Hh];     // hidden after layer 1
__device__ int   g_cnt[Nn];                 // in-degree counts
__device__ int   g_rowptr[Nn + 1];          // CSR row pointers (by dst)
__device__ int   g_cur[Nn];                 // fill cursors
__device__ int   g_csr_src[Ee];             // CSR: source node per edge
__device__ float g_csr_nrm[Ee];             // CSR: dinv[s]*ew*dinv[d]
__device__ int   g_not_i64;                 // 1 if edge_index is int32

__device__ __forceinline__ int ld_idx(const int* __restrict__ p, int i, int is64) {
    return is64 ? p[2 * i] : p[i];
}

// ---------------- init: zero counters + reset dtype flag ----------------
__global__ void k_init() {
    int i = blockIdx.x * blockDim.x + threadIdx.x;
    if (i < Nn) { g_cnt[i] = 0; g_deg[i] = 0.f; }
    if (i == 0) g_not_i64 = 0;
}

// ---------------- dtype detection (int64 => odd words all zero) ------------
__global__ void k_detect(const int* __restrict__ ei) {
    int e = blockIdx.x * blockDim.x + threadIdx.x;
    if (e >= Ee) return;
    if (ei[2 * e + 1] != 0) atomicOr(&g_not_i64, 1);
}

// ---------------- node norms: one warp per node ----------------
__global__ void k_norm(const float* __restrict__ x) {
    int node = (blockIdx.x * blockDim.x + threadIdx.x) >> 5;
    int lane = threadIdx.x & 31;
    if (node >= Nn) return;
    float4 v = ((const float4*)(x + (size_t)node * Hh))[lane];
    float ss = v.x * v.x + v.y * v.y + v.z * v.z + v.w * v.w;
    #pragma unroll
    for (int o = 16; o; o >>= 1) ss += __shfl_xor_sync(0xffffffffu, ss, o);
    if (lane == 0) g_norm[node] = fmaxf(sqrtf(ss), 1e-8f);
}

// ------- edge weights + degree + histogram: one warp per edge --------------
__global__ void k_edge(const float* __restrict__ x,
                       const int* __restrict__ ei,
                       const int* __restrict__ sat) {
    int e = (blockIdx.x * blockDim.x + threadIdx.x) >> 5;
    int lane = threadIdx.x & 31;
    if (e >= Ee) return;
    int is64 = (g_not_i64 == 0);
    unsigned s = (unsigned)ld_idx(ei, e, is64);
    unsigned d = (unsigned)ld_idx(ei, Ee + e, is64);
    if (s >= Nn || d >= Nn) return;   // never fault
    float4 a = ((const float4*)(x + (size_t)s * Hh))[lane];
    float4 b = ((const float4*)(x + (size_t)d * Hh))[lane];
    float dot = a.x * b.x + a.y * b.y + a.z * b.z + a.w * b.w;
    #pragma unroll
    for (int o = 16; o; o >>= 1) dot += __shfl_xor_sync(0xffffffffu, dot, o);
    if (lane == 0) {
        float sim = dot / (g_norm[s] * g_norm[d]);
        int ss_ = ld_idx(sat, (int)s, is64);
        int sd_ = ld_idx(sat, (int)d, is64);
        float f = (ss_ != sd_) ? 0.36787944117144233f : 1.0f;  // exp(-1)
        float ew = fmaxf(sim * f, 1e-4f);
        g_ew[e] = ew;
        atomicAdd(&g_deg[d], ew);
        atomicAdd(&g_cnt[d], 1);
    }
}

// ---------------- dinv = (deg + 1)^-0.5 ----------------
__global__ void k_dinv() {
    int i = blockIdx.x * blockDim.x + threadIdx.x;
    if (i < Nn) g_dinv[i] = rsqrtf(g_deg[i] + 1.0f);
}

// ---------------- single-block prefix scan over g_cnt -> g_rowptr/g_cur ----
__global__ __launch_bounds__(1024) void k_scan() {
    __shared__ int sh[1024];
    const int t = threadIdx.x;
    const int CH = (Nn + 1023) / 1024;      // 49
    int beg = t * CH;
    int end = beg + CH; if (end > Nn) end = Nn;
    int sum = 0;
    for (int i = beg; i < end; i++) sum += g_cnt[i];
    sh[t] = sum;
    __syncthreads();
    for (int off = 1; off < 1024; off <<= 1) {
        int v = 0;
        if (t >= off) v = sh[t - off];
        __syncthreads();
        if (t >= off) sh[t] += v;
        __syncthreads();
    }
    int run = (t == 0) ? 0 : sh[t - 1];
    for (int i = beg; i < end; i++) {
        g_rowptr[i] = run;
        g_cur[i]    = run;
        run += g_cnt[i];
    }
    if (t == 1023) g_rowptr[Nn] = sh[1023];
}

// ---------------- CSR fill: thread per edge ----------------
__global__ void k_fill(const int* __restrict__ ei) {
    int e = blockIdx.x * blockDim.x + threadIdx.x;
    if (e >= Ee) return;
    int is64 = (g_not_i64 == 0);
    unsigned s = (unsigned)ld_idx(ei, e, is64);
    unsigned d = (unsigned)ld_idx(ei, Ee + e, is64);
    if (s >= Nn || d >= Nn) return;
    float nrm = g_dinv[s] * g_ew[e] * g_dinv[d];
    int pos = atomicAdd(&g_cur[d], 1);
    g_csr_src[pos] = (int)s;
    g_csr_nrm[pos] = nrm;
}

// ---------------- GEMM: g_xt = A @ W ;  A = x param (layer 0) or g_h1 ------
__global__ __launch_bounds__(256) void k_gemm128(const float* __restrict__ Aext,
                                                 const float* __restrict__ W,
                                                 int use_h1) {
    __shared__ float Xs[64][33];
    __shared__ __align__(16) float Ws[32][128];
    const float* __restrict__ A = use_h1 ? (const float*)g_h1 : Aext;
    int tid = threadIdx.x;
    int tx = tid & 15;
    int rt = tid >> 4;
    int row0 = blockIdx.x * 64;

    float acc[4][8];
    #pragma unroll
    for (int i = 0; i < 4; i++)
        #pragma unroll
        for (int j = 0; j < 8; j++) acc[i][j] = 0.f;

    for (int kc = 0; kc < 4; kc++) {
        #pragma unroll
        for (int i = 0; i < 8; i++) {
            int idx = tid + i * 256;
            int r = idx >> 5, k = idx & 31;
            int gr = row0 + r;
            Xs[r][k] = (gr < Nn) ? A[(size_t)gr * 128 + kc * 32 + k] : 0.f;
        }
        #pragma unroll
        for (int i = 0; i < 16; i++) {
            int idx = tid + i * 256;
            int k = idx >> 7, c = idx & 127;
            Ws[k][c] = W[(size_t)(kc * 32 + k) * 128 + c];
        }
        __syncthreads();
        #pragma unroll
        for (int k = 0; k < 32; k++) {
            float4 w0 = *(const float4*)&Ws[k][tx * 8];
            float4 w1 = *(const float4*)&Ws[k][tx * 8 + 4];
            #pragma unroll
            for (int i = 0; i < 4; i++) {
                float xv = Xs[rt * 4 + i][k];
                acc[i][0] += xv * w0.x; acc[i][1] += xv * w0.y;
                acc[i][2] += xv * w0.z; acc[i][3] += xv * w0.w;
                acc[i][4] += xv * w1.x; acc[i][5] += xv * w1.y;
                acc[i][6] += xv * w1.z; acc[i][7] += xv * w1.w;
            }
        }
        __syncthreads();
    }
    #pragma unroll
    for (int i = 0; i < 4; i++) {
        int gr = row0 + rt * 4 + i;
        if (gr < Nn) {
            float4* cp = (float4*)(g_xt + (size_t)gr * 128 + tx * 8);
            cp[0] = make_float4(acc[i][0], acc[i][1], acc[i][2], acc[i][3]);
            cp[1] = make_float4(acc[i][4], acc[i][5], acc[i][6], acc[i][7]);
        }
    }
}

// ----- fused CSR aggregation + self-loop + bias + relu: warp per node ------
__global__ void k_aggc(const float* __restrict__ b, float* __restrict__ outext,
                       int to_h1) {
    int node = (blockIdx.x * blockDim.x + threadIdx.x) >> 5;
    int lane = threadIdx.x & 31;
    if (node >= Nn) return;
    int beg = g_rowptr[node];
    int end = g_rowptr[node + 1];

    float4 acc0 = make_float4(0.f, 0.f, 0.f, 0.f);
    float4 acc1 = make_float4(0.f, 0.f, 0.f, 0.f);

    int p = beg;
    for (; p + 1 < end; p += 2) {
        int   s0 = g_csr_src[p],     s1 = g_csr_src[p + 1];
        float n0 = g_csr_nrm[p],     n1 = g_csr_nrm[p + 1];
        float4 v0 = ((const float4*)(g_xt + (size_t)s0 * Hh))[lane];
        float4 v1 = ((const float4*)(g_xt + (size_t)s1 * Hh))[lane];
        acc0.x += v0.x * n0; acc0.y += v0.y * n0; acc0.z += v0.z * n0; acc0.w += v0.w * n0;
        acc1.x += v1.x * n1; acc1.y += v1.y * n1; acc1.z += v1.z * n1; acc1.w += v1.w * n1;
    }
    if (p < end) {
        int   s0 = g_csr_src[p];
        float n0 = g_csr_nrm[p];
        float4 v0 = ((const float4*)(g_xt + (size_t)s0 * Hh))[lane];
        acc0.x += v0.x * n0; acc0.y += v0.y * n0; acc0.z += v0.z * n0; acc0.w += v0.w * n0;
    }

    float di = g_dinv[node];
    float d2 = di * di;
    float4 self = ((const float4*)(g_xt + (size_t)node * Hh))[lane];
    float4 bb = ((const float4*)b)[lane];
    float4 r;
    r.x = fmaxf(acc0.x + acc1.x + self.x * d2 + bb.x, 0.f);
    r.y = fmaxf(acc0.y + acc1.y + self.y * d2 + bb.y, 0.f);
    r.z = fmaxf(acc0.z + acc1.z + self.z * d2 + bb.z, 0.f);
    r.w = fmaxf(acc0.w + acc1.w + self.w * d2 + bb.w, 0.f);

    float4* dst = to_h1 ? (float4*)(g_h1 + (size_t)node * Hh)
                        : (float4*)(outext + (size_t)node * Hh);
    dst[lane] = r;
}

// ---------------- head: y = h @ Wc + bc, warp per node ---------------------
__global__ void k_y(const float* __restrict__ h, const float* __restrict__ Wc,
                    const float* __restrict__ bc, float* __restrict__ y) {
    int node = (blockIdx.x * blockDim.x + threadIdx.x) >> 5;
    int lane = threadIdx.x & 31;
    if (node >= Nn) return;
    float4 hv = ((const float4*)(h + (size_t)node * Hh))[lane];
    float4 wv = ((const float4*)Wc)[lane];
    float dot = hv.x * wv.x + hv.y * wv.y + hv.z * wv.z + hv.w * wv.w;
    #pragma unroll
    for (int o = 16; o; o >>= 1) dot += __shfl_xor_sync(0xffffffffu, dot, o);
    if (lane == 0) y[node] = dot + bc[0];
}

// ---------------- launch ----------------
extern "C" void kernel_launch(void* const* d_in, const int* in_sizes, int n_in,
                              void* d_out, int out_size) {
    // runtime input-ordering via size fingerprint
    int ix = 0, iei = 1, isa = 2, iW1 = 3, ib1 = 4, iW2 = 5, ib2 = 6, iWc = 7, ibc = 8;
    if (n_in >= 9 && in_sizes[0] != 6400000) {
        if (in_sizes[0] == 16384 && in_sizes[1] == 16384) {
            iW1 = 0; iW2 = 1; iWc = 2; ib1 = 3; ib2 = 4; ibc = 5; iei = 6; isa = 7; ix = 8;
        } else {
            int c128a = -1, c128b = -1, c128c = -1, w16a = -1, w16b = -1;
            for (int i = 0; i < n_in; i++) {
                int s = in_sizes[i];
                if (s == 6400000) ix = i;
                else if (s == 1600000 || s == 3200000) iei = i;
                else if (s == 50000 || s == 100000) isa = i;
                else if (s == 16384) { if (w16a < 0) w16a = i; else w16b = i; }
                else if (s == 128) { if (c128a < 0) c128a = i; else if (c128b < 0) c128b = i; else c128c = i; }
                else if (s == 1) ibc = i;
            }
            iW1 = w16a; iW2 = w16b; ib1 = c128a; ib2 = c128b; iWc = c128c;
        }
    }

    const float* x  = (const float*)d_in[ix];
    const int*   ei = (const int*)d_in[iei];
    const int*   sa = (const int*)d_in[isa];
    const float* W1 = (const float*)d_in[iW1];
    const float* b1 = (const float*)d_in[ib1];
    const float* W2 = (const float*)d_in[iW2];
    const float* b2 = (const float*)d_in[ib2];
    const float* Wc = (const float*)d_in[iWc];
    const float* bc = (const float*)d_in[ibc];

    float* out  = (float*)d_out;
    float* yout = out;        // [N]
    float* hout = out + Nn;   // [N, 128]

    const int T = 256;
    const int gN      = (Nn + T - 1) / T;
    const int gNwarp  = (Nn + 7) / 8;
    const int gEwarp  = (Ee + 7) / 8;
    const int gE      = (Ee + T - 1) / T;
    const int gGemm   = (Nn + 63) / 64;

    // init + dtype detection
    k_init<<<gN, T>>>();
    k_detect<<<gE, T>>>(ei);

    // edge weights + degree + histogram
    k_norm<<<gNwarp, T>>>(x);
    k_edge<<<gEwarp, T>>>(x, ei, sa);

    // CSR build
    k_scan<<<1, 1024>>>();
    k_dinv<<<gN, T>>>();
    k_fill<<<gE, T>>>(ei);

    // layer 1
    k_gemm128<<<gGemm, T>>>(x, W1, 0);
    k_aggc<<<gNwarp, T>>>(b1, nullptr, 1);

    // layer 2
    k_gemm128<<<gGemm, T>>>(x /*unused*/, W2, 1);
    k_aggc<<<gNwarp, T>>>(b2, hout, 0);

    // head
    k_y<<<gNwarp, T>>>(hout, Wc, bc, yout);
}

// round 6
// speedup vs baseline: 1.8425x; 1.0533x over previous
#include <cuda_runtime.h>
#include <cuda_fp16.h>

#define Nn 50000
#define Ee 800000
#define Hh 128

// ---------------- scratch (device globals; NEVER passed as kernel args) ----
__device__ __half g_xh[(size_t)Nn * Hh];    // x rows normalized, fp16
__device__ float g_ew[Ee];
__device__ float g_deg[Nn];
__device__ float g_dinv[Nn];
__device__ float g_xt[(size_t)Nn * Hh];     // lin output of current layer
__device__ float g_h1[(size_t)Nn * Hh];     // hidden after layer 1
__device__ int   g_cnt[Nn];                 // in-degree counts
__device__ int   g_rowptr[Nn + 1];          // CSR row pointers (by dst)
__device__ int   g_cur[Nn];                 // fill cursors
__device__ int   g_csr_src[Ee];             // CSR: source node per edge
__device__ float g_csr_nrm[Ee];             // CSR: dinv[s]*ew*dinv[d]
__device__ int   g_not_i64;                 // 1 if edge_index is int32

__device__ __forceinline__ int ld_idx(const int* __restrict__ p, int i, int is64) {
    return is64 ? p[2 * i] : p[i];
}

// ---------------- init: zero counters + reset dtype flag ----------------
__global__ void k_init() {
    int i = blockIdx.x * blockDim.x + threadIdx.x;
    if (i < Nn) { g_cnt[i] = 0; g_deg[i] = 0.f; }
    if (i == 0) g_not_i64 = 0;
}

// ---------------- dtype detection (int64 => odd words all zero) ------------
__global__ void k_detect(const int* __restrict__ ei) {
    int e = blockIdx.x * blockDim.x + threadIdx.x;
    if (e >= Ee) return;
    if (ei[2 * e + 1] != 0) atomicOr(&g_not_i64, 1);
}

// ------- normalize rows of x into fp16: one warp per node ------------------
__global__ void k_xnorm(const float* __restrict__ x) {
    int node = (blockIdx.x * blockDim.x + threadIdx.x) >> 5;
    int lane = threadIdx.x & 31;
    if (node >= Nn) return;
    float4 v = ((const float4*)(x + (size_t)node * Hh))[lane];
    float ss = v.x * v.x + v.y * v.y + v.z * v.z + v.w * v.w;
    #pragma unroll
    for (int o = 16; o; o >>= 1) ss += __shfl_xor_sync(0xffffffffu, ss, o);
    float inv = 1.0f / fmaxf(sqrtf(ss), 1e-8f);
    __half2 h0 = __floats2half2_rn(v.x * inv, v.y * inv);
    __half2 h1 = __floats2half2_rn(v.z * inv, v.w * inv);
    uint2 pk;
    pk.x = *(unsigned*)&h0;
    pk.y = *(unsigned*)&h1;
    ((uint2*)(g_xh + (size_t)node * Hh))[lane] = pk;
}

// ------- edge weights + degree + histogram: one warp per edge --------------
__global__ void k_edge(const int* __restrict__ ei,
                       const int* __restrict__ sat) {
    int e = (blockIdx.x * blockDim.x + threadIdx.x) >> 5;
    int lane = threadIdx.x & 31;
    if (e >= Ee) return;
    int is64 = (g_not_i64 == 0);
    unsigned s = (unsigned)ld_idx(ei, e, is64);
    unsigned d = (unsigned)ld_idx(ei, Ee + e, is64);
    if (s >= Nn || d >= Nn) return;   // never fault
    uint2 pa = ((const uint2*)(g_xh + (size_t)s * Hh))[lane];
    uint2 pb = ((const uint2*)(g_xh + (size_t)d * Hh))[lane];
    float2 a0 = __half22float2(*(__half2*)&pa.x);
    float2 a1 = __half22float2(*(__half2*)&pa.y);
    float2 b0 = __half22float2(*(__half2*)&pb.x);
    float2 b1 = __half22float2(*(__half2*)&pb.y);
    float dot = a0.x * b0.x + a0.y * b0.y + a1.x * b1.x + a1.y * b1.y;
    #pragma unroll
    for (int o = 16; o; o >>= 1) dot += __shfl_xor_sync(0xffffffffu, dot, o);
    if (lane == 0) {
        int ss_ = ld_idx(sat, (int)s, is64);
        int sd_ = ld_idx(sat, (int)d, is64);
        float f = (ss_ != sd_) ? 0.36787944117144233f : 1.0f;  // exp(-1)
        float ew = fmaxf(dot * f, 1e-4f);
        g_ew[e] = ew;
        atomicAdd(&g_deg[d], ew);
        atomicAdd(&g_cnt[d], 1);
    }
}

// ---------------- dinv = (deg + 1)^-0.5 ----------------
__global__ void k_dinv() {
    int i = blockIdx.x * blockDim.x + threadIdx.x;
    if (i < Nn) g_dinv[i] = rsqrtf(g_deg[i] + 1.0f);
}

// ---------------- single-block prefix scan over g_cnt -> g_rowptr/g_cur ----
__global__ __launch_bounds__(1024) void k_scan() {
    __shared__ int sh[1024];
    const int t = threadIdx.x;
    const int CH = (Nn + 1023) / 1024;      // 49
    int beg = t * CH;
    int end = beg + CH; if (end > Nn) end = Nn;
    int sum = 0;
    for (int i = beg; i < end; i++) sum += g_cnt[i];
    sh[t] = sum;
    __syncthreads();
    for (int off = 1; off < 1024; off <<= 1) {
        int v = 0;
        if (t >= off) v = sh[t - off];
        __syncthreads();
        if (t >= off) sh[t] += v;
        __syncthreads();
    }
    int run = (t == 0) ? 0 : sh[t - 1];
    for (int i = beg; i < end; i++) {
        g_rowptr[i] = run;
        g_cur[i]    = run;
        run += g_cnt[i];
    }
    if (t == 1023) g_rowptr[Nn] = sh[1023];
}

// ---------------- CSR fill: thread per edge ----------------
__global__ void k_fill(const int* __restrict__ ei) {
    int e = blockIdx.x * blockDim.x + threadIdx.x;
    if (e >= Ee) return;
    int is64 = (g_not_i64 == 0);
    unsigned s = (unsigned)ld_idx(ei, e, is64);
    unsigned d = (unsigned)ld_idx(ei, Ee + e, is64);
    if (s >= Nn || d >= Nn) return;
    float nrm = g_dinv[s] * g_ew[e] * g_dinv[d];
    int pos = atomicAdd(&g_cur[d], 1);
    g_csr_src[pos] = (int)s;
    g_csr_nrm[pos] = nrm;
}

// ---------------- GEMM: g_xt = A @ W ;  A = x param (layer 0) or g_h1 ------
__global__ __launch_bounds__(256) void k_gemm128(const float* __restrict__ Aext,
                                                 const float* __restrict__ W,
                                                 int use_h1) {
    __shared__ float Xs[64][33];
    __shared__ __align__(16) float Ws[32][128];
    const float* __restrict__ A = use_h1 ? (const float*)g_h1 : Aext;
    int tid = threadIdx.x;
    int tx = tid & 15;
    int rt = tid >> 4;
    int row0 = blockIdx.x * 64;

    float acc[4][8];
    #pragma unroll
    for (int i = 0; i < 4; i++)
        #pragma unroll
        for (int j = 0; j < 8; j++) acc[i][j] = 0.f;

    for (int kc = 0; kc < 4; kc++) {
        #pragma unroll
        for (int i = 0; i < 8; i++) {
            int idx = tid + i * 256;
            int r = idx >> 5, k = idx & 31;
            int gr = row0 + r;
            Xs[r][k] = (gr < Nn) ? A[(size_t)gr * 128 + kc * 32 + k] : 0.f;
        }
        #pragma unroll
        for (int i = 0; i < 16; i++) {
            int idx = tid + i * 256;
            int k = idx >> 7, c = idx & 127;
            Ws[k][c] = W[(size_t)(kc * 32 + k) * 128 + c];
        }
        __syncthreads();
        #pragma unroll
        for (int k = 0; k < 32; k++) {
            float4 w0 = *(const float4*)&Ws[k][tx * 8];
            float4 w1 = *(const float4*)&Ws[k][tx * 8 + 4];
            #pragma unroll
            for (int i = 0; i < 4; i++) {
                float xv = Xs[rt * 4 + i][k];
                acc[i][0] += xv * w0.x; acc[i][1] += xv * w0.y;
                acc[i][2] += xv * w0.z; acc[i][3] += xv * w0.w;
                acc[i][4] += xv * w1.x; acc[i][5] += xv * w1.y;
                acc[i][6] += xv * w1.z; acc[i][7] += xv * w1.w;
            }
        }
        __syncthreads();
    }
    #pragma unroll
    for (int i = 0; i < 4; i++) {
        int gr = row0 + rt * 4 + i;
        if (gr < Nn) {
            float4* cp = (float4*)(g_xt + (size_t)gr * 128 + tx * 8);
            cp[0] = make_float4(acc[i][0], acc[i][1], acc[i][2], acc[i][3]);
            cp[1] = make_float4(acc[i][4], acc[i][5], acc[i][6], acc[i][7]);
        }
    }
}

// ----- fused CSR aggregation + self-loop + bias + relu (+optional head) ----
// to_h1=1: write g_h1.  to_h1=0: write outext AND y = h.Wc + bc
__global__ void k_aggc(const float* __restrict__ b, float* __restrict__ outext,
                       const float* __restrict__ Wc, const float* __restrict__ bc,
                       float* __restrict__ y, int to_h1) {
    int node = (blockIdx.x * blockDim.x + threadIdx.x) >> 5;
    int lane = threadIdx.x & 31;
    if (node >= Nn) return;
    int beg = g_rowptr[node];
    int end = g_rowptr[node + 1];

    float4 acc0 = make_float4(0.f, 0.f, 0.f, 0.f);
    float4 acc1 = make_float4(0.f, 0.f, 0.f, 0.f);

    int p = beg;
    for (; p + 1 < end; p += 2) {
        int   s0 = g_csr_src[p],     s1 = g_csr_src[p + 1];
        float n0 = g_csr_nrm[p],     n1 = g_csr_nrm[p + 1];
        float4 v0 = ((const float4*)(g_xt + (size_t)s0 * Hh))[lane];
        float4 v1 = ((const float4*)(g_xt + (size_t)s1 * Hh))[lane];
        acc0.x += v0.x * n0; acc0.y += v0.y * n0; acc0.z += v0.z * n0; acc0.w += v0.w * n0;
        acc1.x += v1.x * n1; acc1.y += v1.y * n1; acc1.z += v1.z * n1; acc1.w += v1.w * n1;
    }
    if (p < end) {
        int   s0 = g_csr_src[p];
        float n0 = g_csr_nrm[p];
        float4 v0 = ((const float4*)(g_xt + (size_t)s0 * Hh))[lane];
        acc0.x += v0.x * n0; acc0.y += v0.y * n0; acc0.z += v0.z * n0; acc0.w += v0.w * n0;
    }

    float di = g_dinv[node];
    float d2 = di * di;
    float4 self = ((const float4*)(g_xt + (size_t)node * Hh))[lane];
    float4 bb = ((const float4*)b)[lane];
    float4 r;
    r.x = fmaxf(acc0.x + acc1.x + self.x * d2 + bb.x, 0.f);
    r.y = fmaxf(acc0.y + acc1.y + self.y * d2 + bb.y, 0.f);
    r.z = fmaxf(acc0.z + acc1.z + self.z * d2 + bb.z, 0.f);
    r.w = fmaxf(acc0.w + acc1.w + self.w * d2 + bb.w, 0.f);

    if (to_h1) {
        ((float4*)(g_h1 + (size_t)node * Hh))[lane] = r;
    } else {
        ((float4*)(outext + (size_t)node * Hh))[lane] = r;
        // fused head: y = h . Wc + bc
        float4 wv = ((const float4*)Wc)[lane];
        float dot = r.x * wv.x + r.y * wv.y + r.z * wv.z + r.w * wv.w;
        #pragma unroll
        for (int o = 16; o; o >>= 1) dot += __shfl_xor_sync(0xffffffffu, dot, o);
        if (lane == 0) y[node] = dot + bc[0];
    }
}

// ---------------- launch ----------------
extern "C" void kernel_launch(void* const* d_in, const int* in_sizes, int n_in,
                              void* d_out, int out_size) {
    // runtime input-ordering via size fingerprint
    int ix = 0, iei = 1, isa = 2, iW1 = 3, ib1 = 4, iW2 = 5, ib2 = 6, iWc = 7, ibc = 8;
    if (n_in >= 9 && in_sizes[0] != 6400000) {
        if (in_sizes[0] == 16384 && in_sizes[1] == 16384) {
            iW1 = 0; iW2 = 1; iWc = 2; ib1 = 3; ib2 = 4; ibc = 5; iei = 6; isa = 7; ix = 8;
        } else {
            int c128a = -1, c128b = -1, c128c = -1, w16a = -1, w16b = -1;
            for (int i = 0; i < n_in; i++) {
                int s = in_sizes[i];
                if (s == 6400000) ix = i;
                else if (s == 1600000 || s == 3200000) iei = i;
                else if (s == 50000 || s == 100000) isa = i;
                else if (s == 16384) { if (w16a < 0) w16a = i; else w16b = i; }
                else if (s == 128) { if (c128a < 0) c128a = i; else if (c128b < 0) c128b = i; else c128c = i; }
                else if (s == 1) ibc = i;
            }
            iW1 = w16a; iW2 = w16b; ib1 = c128a; ib2 = c128b; iWc = c128c;
        }
    }

    const float* x  = (const float*)d_in[ix];
    const int*   ei = (const int*)d_in[iei];
    const int*   sa = (const int*)d_in[isa];
    const float* W1 = (const float*)d_in[iW1];
    const float* b1 = (const float*)d_in[ib1];
    const float* W2 = (const float*)d_in[iW2];
    const float* b2 = (const float*)d_in[ib2];
    const float* Wc = (const float*)d_in[iWc];
    const float* bc = (const float*)d_in[ibc];

    float* out  = (float*)d_out;
    float* yout = out;        // [N]
    float* hout = out + Nn;   // [N, 128]

    const int T = 256;
    const int gN      = (Nn + T - 1) / T;
    const int gNwarp  = (Nn + 7) / 8;
    const int gEwarp  = (Ee + 7) / 8;
    const int gE      = (Ee + T - 1) / T;
    const int gGemm   = (Nn + 63) / 64;

    // init + dtype detection
    k_init<<<gN, T>>>();
    k_detect<<<gE, T>>>(ei);

    // normalized fp16 x, then edge weights + degree + histogram
    k_xnorm<<<gNwarp, T>>>(x);
    k_edge<<<gEwarp, T>>>(ei, sa);

    // CSR build
    k_scan<<<1, 1024>>>();
    k_dinv<<<gN, T>>>();
    k_fill<<<gE, T>>>(ei);

    // layer 1
    k_gemm128<<<gGemm, T>>>(x, W1, 0);
    k_aggc<<<gNwarp, T>>>(b1, nullptr, nullptr, nullptr, nullptr, 1);

    // layer 2 (+fused head)
    k_gemm128<<<gGemm, T>>>(x /*unused*/, W2, 1);
    k_aggc<<<gNwarp, T>>>(b2, hout, Wc, bc, yout, 0);
}

// round 7
// speedup vs baseline: 2.8794x; 1.5628x over previous
#include <cuda_runtime.h>
#include <cuda_fp16.h>
#include <mma.h>

using namespace nvcuda;

#define Nn 50000
#define Ee 800000
#define Hh 128
#define SK 136   // padded smem stride (halves): 272B, 16B/32B aligned

// ---------------- scratch (device globals; NEVER passed as kernel args) ----
__device__ __half g_xh[(size_t)Nn * Hh];    // x rows normalized, fp16 (for cosine)
__device__ __half g_ah[(size_t)Nn * Hh];    // GEMM A operand, fp16 (x or h1)
__device__ __half g_W1h[Hh * Hh];
__device__ __half g_W2h[Hh * Hh];
__device__ float g_ew[Ee];
__device__ float g_deg[Nn];
__device__ float g_dinv[Nn];
__device__ float g_xt[(size_t)Nn * Hh];     // lin output of current layer (fp32)
__device__ int   g_cnt[Nn];
__device__ int   g_rowptr[Nn + 1];
__device__ int   g_cur[Nn];
__device__ int   g_csr_src[Ee];
__device__ float g_csr_nrm[Ee];
__device__ int   g_not_i64;

__device__ __forceinline__ int ld_idx(const int* __restrict__ p, int i, int is64) {
    return is64 ? p[2 * i] : p[i];
}

// ---------------- init ----------------
__global__ void k_init() {
    int i = blockIdx.x * blockDim.x + threadIdx.x;
    if (i < Nn) { g_cnt[i] = 0; g_deg[i] = 0.f; }
    if (i == 0) g_not_i64 = 0;
}

__global__ void k_detect(const int* __restrict__ ei) {
    int e = blockIdx.x * blockDim.x + threadIdx.x;
    if (e >= Ee) return;
    if (ei[2 * e + 1] != 0) atomicOr(&g_not_i64, 1);
}

// ------- normalize rows of x into fp16 (g_xh) AND raw fp16 copy (g_ah) -----
__global__ void k_xprep(const float* __restrict__ x) {
    int node = (blockIdx.x * blockDim.x + threadIdx.x) >> 5;
    int lane = threadIdx.x & 31;
    if (node >= Nn) return;
    float4 v = ((const float4*)(x + (size_t)node * Hh))[lane];
    float ss = v.x * v.x + v.y * v.y + v.z * v.z + v.w * v.w;
    #pragma unroll
    for (int o = 16; o; o >>= 1) ss += __shfl_xor_sync(0xffffffffu, ss, o);
    float inv = 1.0f / fmaxf(sqrtf(ss), 1e-8f);
    __half2 n0 = __floats2half2_rn(v.x * inv, v.y * inv);
    __half2 n1 = __floats2half2_rn(v.z * inv, v.w * inv);
    uint2 pn; pn.x = *(unsigned*)&n0; pn.y = *(unsigned*)&n1;
    ((uint2*)(g_xh + (size_t)node * Hh))[lane] = pn;
    __half2 r0 = __floats2half2_rn(v.x, v.y);
    __half2 r1 = __floats2half2_rn(v.z, v.w);
    uint2 pr; pr.x = *(unsigned*)&r0; pr.y = *(unsigned*)&r1;
    ((uint2*)(g_ah + (size_t)node * Hh))[lane] = pr;
}

// ---------------- convert W1, W2 to fp16 ----------------
__global__ void k_w2h(const float* __restrict__ W1, const float* __restrict__ W2) {
    int i = blockIdx.x * blockDim.x + threadIdx.x;
    if (i < Hh * Hh) g_W1h[i] = __float2half_rn(W1[i]);
    else if (i < 2 * Hh * Hh) g_W2h[i - Hh * Hh] = __float2half_rn(W2[i - Hh * Hh]);
}

// ------- edge weights + degree + histogram: 16 lanes per edge --------------
__global__ void k_edge(const int* __restrict__ ei,
                       const int* __restrict__ sat) {
    int gt = blockIdx.x * blockDim.x + threadIdx.x;
    int e = gt >> 4;                 // 2 edges per warp
    int sub = threadIdx.x & 15;      // lane within edge group
    if (e >= Ee) return;
    int is64 = (g_not_i64 == 0);
    unsigned s = (unsigned)ld_idx(ei, e, is64);
    unsigned d = (unsigned)ld_idx(ei, Ee + e, is64);
    if (s >= Nn || d >= Nn) return;   // never fault
    uint4 pa = ((const uint4*)(g_xh + (size_t)s * Hh))[sub];   // 8 halves
    uint4 pb = ((const uint4*)(g_xh + (size_t)d * Hh))[sub];
    float2 a0 = __half22float2(*(__half2*)&pa.x);
    float2 a1 = __half22float2(*(__half2*)&pa.y);
    float2 a2 = __half22float2(*(__half2*)&pa.z);
    float2 a3 = __half22float2(*(__half2*)&pa.w);
    float2 b0 = __half22float2(*(__half2*)&pb.x);
    float2 b1 = __half22float2(*(__half2*)&pb.y);
    float2 b2 = __half22float2(*(__half2*)&pb.z);
    float2 b3 = __half22float2(*(__half2*)&pb.w);
    float dot = a0.x * b0.x + a0.y * b0.y + a1.x * b1.x + a1.y * b1.y
              + a2.x * b2.x + a2.y * b2.y + a3.x * b3.x + a3.y * b3.y;
    #pragma unroll
    for (int o = 8; o; o >>= 1) dot += __shfl_xor_sync(0xffffffffu, dot, o);
    if (sub == 0) {
        int ss_ = ld_idx(sat, (int)s, is64);
        int sd_ = ld_idx(sat, (int)d, is64);
        float f = (ss_ != sd_) ? 0.36787944117144233f : 1.0f;  // exp(-1)
        float ew = fmaxf(dot * f, 1e-4f);
        g_ew[e] = ew;
        atomicAdd(&g_deg[d], ew);
        atomicAdd(&g_cnt[d], 1);
    }
}

// ---------------- dinv = (deg + 1)^-0.5 ----------------
__global__ void k_dinv() {
    int i = blockIdx.x * blockDim.x + threadIdx.x;
    if (i < Nn) g_dinv[i] = rsqrtf(g_deg[i] + 1.0f);
}

// ---------------- single-block prefix scan ----------------
__global__ __launch_bounds__(1024) void k_scan() {
    __shared__ int sh[1024];
    const int t = threadIdx.x;
    const int CH = (Nn + 1023) / 1024;
    int beg = t * CH;
    int end = beg + CH; if (end > Nn) end = Nn;
    int sum = 0;
    for (int i = beg; i < end; i++) sum += g_cnt[i];
    sh[t] = sum;
    __syncthreads();
    for (int off = 1; off < 1024; off <<= 1) {
        int v = 0;
        if (t >= off) v = sh[t - off];
        __syncthreads();
        if (t >= off) sh[t] += v;
        __syncthreads();
    }
    int run = (t == 0) ? 0 : sh[t - 1];
    for (int i = beg; i < end; i++) {
        g_rowptr[i] = run;
        g_cur[i]    = run;
        run += g_cnt[i];
    }
    if (t == 1023) g_rowptr[Nn] = sh[1023];
}

// ---------------- CSR fill ----------------
__global__ void k_fill(const int* __restrict__ ei) {
    int e = blockIdx.x * blockDim.x + threadIdx.x;
    if (e >= Ee) return;
    int is64 = (g_not_i64 == 0);
    unsigned s = (unsigned)ld_idx(ei, e, is64);
    unsigned d = (unsigned)ld_idx(ei, Ee + e, is64);
    if (s >= Nn || d >= Nn) return;
    float nrm = g_dinv[s] * g_ew[e] * g_dinv[d];
    int pos = atomicAdd(&g_cur[d], 1);
    g_csr_src[pos] = (int)s;
    g_csr_nrm[pos] = nrm;
}

// ------------- tensor-core GEMM: g_xt = g_ah @ W(half), fp32 acc -----------
// Block: 128 rows x 128 cols, 8 warps, each warp 16 rows x 128 cols.
__global__ __launch_bounds__(256) void k_gemmh(int which) {
    extern __shared__ __align__(32) __half sh[];
    __half* Ah = sh;               // [128][SK]
    __half* Wh = sh + 128 * SK;    // [128][SK]
    const __half* __restrict__ W = which ? g_W2h : g_W1h;
    int tid = threadIdx.x;
    int row0 = blockIdx.x * 128;

    // stage W (128x128 halves)
    for (int i = tid; i < 128 * 16; i += 256) {
        int r = i >> 4, c = i & 15;
        *((uint4*)(Wh + r * SK + c * 8)) = ((const uint4*)(W + r * 128 + c * 8))[0];
    }
    // stage A tile (guarded)
    for (int i = tid; i < 128 * 16; i += 256) {
        int r = i >> 4, c = i & 15;
        int gr = row0 + r;
        uint4 v = make_uint4(0u, 0u, 0u, 0u);
        if (gr < Nn) v = ((const uint4*)(g_ah + (size_t)gr * 128 + c * 8))[0];
        *((uint4*)(Ah + r * SK + c * 8)) = v;
    }
    __syncthreads();

    int w = tid >> 5;   // warp id 0..7 -> rows w*16
    wmma::fragment<wmma::accumulator, 16, 16, 16, float> acc[8];
    #pragma unroll
    for (int n = 0; n < 8; n++) wmma::fill_fragment(acc[n], 0.0f);

    #pragma unroll
    for (int k = 0; k < 8; k++) {
        wmma::fragment<wmma::matrix_a, 16, 16, 16, __half, wmma::row_major> af;
        wmma::load_matrix_sync(af, Ah + (w * 16) * SK + k * 16, SK);
        #pragma unroll
        for (int n = 0; n < 8; n++) {
            wmma::fragment<wmma::matrix_b, 16, 16, 16, __half, wmma::row_major> bf;
            wmma::load_matrix_sync(bf, Wh + (k * 16) * SK + n * 16, SK);
            wmma::mma_sync(acc[n], af, bf, acc[n]);
        }
    }

    int gr0 = row0 + w * 16;
    if (gr0 < Nn) {   // Nn is a multiple of 16: tile fully valid or fully out
        #pragma unroll
        for (int n = 0; n < 8; n++)
            wmma::store_matrix_sync(g_xt + (size_t)gr0 * 128 + n * 16, acc[n],
                                    128, wmma::mem_row_major);
    }
}

// ----- fused CSR aggregation + self-loop + bias + relu (+optional head) ----
// to_h1=1: write g_ah (fp16, next GEMM A).  to_h1=0: write outext AND y head.
__global__ void k_aggc(const float* __restrict__ b, float* __restrict__ outext,
                       const float* __restrict__ Wc, const float* __restrict__ bc,
                       float* __restrict__ y, int to_h1) {
    int node = (blockIdx.x * blockDim.x + threadIdx.x) >> 5;
    int lane = threadIdx.x & 31;
    if (node >= Nn) return;
    int beg = g_rowptr[node];
    int end = g_rowptr[node + 1];

    float4 acc0 = make_float4(0.f, 0.f, 0.f, 0.f);
    float4 acc1 = make_float4(0.f, 0.f, 0.f, 0.f);

    int p = beg;
    for (; p + 1 < end; p += 2) {
        int   s0 = g_csr_src[p],     s1 = g_csr_src[p + 1];
        float n0 = g_csr_nrm[p],     n1 = g_csr_nrm[p + 1];
        float4 v0 = ((const float4*)(g_xt + (size_t)s0 * Hh))[lane];
        float4 v1 = ((const float4*)(g_xt + (size_t)s1 * Hh))[lane];
        acc0.x += v0.x * n0; acc0.y += v0.y * n0; acc0.z += v0.z * n0; acc0.w += v0.w * n0;
        acc1.x += v1.x * n1; acc1.y += v1.y * n1; acc1.z += v1.z * n1; acc1.w += v1.w * n1;
    }
    if (p < end) {
        int   s0 = g_csr_src[p];
        float n0 = g_csr_nrm[p];
        float4 v0 = ((const float4*)(g_xt + (size_t)s0 * Hh))[lane];
        acc0.x += v0.x * n0; acc0.y += v0.y * n0; acc0.z += v0.z * n0; acc0.w += v0.w * n0;
    }

    float di = g_dinv[node];
    float d2 = di * di;
    float4 self = ((const float4*)(g_xt + (size_t)node * Hh))[lane];
    float4 bb = ((const float4*)b)[lane];
    float4 r;
    r.x = fmaxf(acc0.x + acc1.x + self.x * d2 + bb.x, 0.f);
    r.y = fmaxf(acc0.y + acc1.y + self.y * d2 + bb.y, 0.f);
    r.z = fmaxf(acc0.z + acc1.z + self.z * d2 + bb.z, 0.f);
    r.w = fmaxf(acc0.w + acc1.w + self.w * d2 + bb.w, 0.f);

    if (to_h1) {
        __half2 h0 = __floats2half2_rn(r.x, r.y);
        __half2 h1 = __floats2half2_rn(r.z, r.w);
        uint2 pk; pk.x = *(unsigned*)&h0; pk.y = *(unsigned*)&h1;
        ((uint2*)(g_ah + (size_t)node * Hh))[lane] = pk;
    } else {
        ((float4*)(outext + (size_t)node * Hh))[lane] = r;
        float4 wv = ((const float4*)Wc)[lane];
        float dot = r.x * wv.x + r.y * wv.y + r.z * wv.z + r.w * wv.w;
        #pragma unroll
        for (int o = 16; o; o >>= 1) dot += __shfl_xor_sync(0xffffffffu, dot, o);
        if (lane == 0) y[node] = dot + bc[0];
    }
}

// ---------------- launch ----------------
extern "C" void kernel_launch(void* const* d_in, const int* in_sizes, int n_in,
                              void* d_out, int out_size) {
    // runtime input-ordering via size fingerprint
    int ix = 0, iei = 1, isa = 2, iW1 = 3, ib1 = 4, iW2 = 5, ib2 = 6, iWc = 7, ibc = 8;
    if (n_in >= 9 && in_sizes[0] != 6400000) {
        if (in_sizes[0] == 16384 && in_sizes[1] == 16384) {
            iW1 = 0; iW2 = 1; iWc = 2; ib1 = 3; ib2 = 4; ibc = 5; iei = 6; isa = 7; ix = 8;
        } else {
            int c128a = -1, c128b = -1, c128c = -1, w16a = -1, w16b = -1;
            for (int i = 0; i < n_in; i++) {
                int s = in_sizes[i];
                if (s == 6400000) ix = i;
                else if (s == 1600000 || s == 3200000) iei = i;
                else if (s == 50000 || s == 100000) isa = i;
                else if (s == 16384) { if (w16a < 0) w16a = i; else w16b = i; }
                else if (s == 128) { if (c128a < 0) c128a = i; else if (c128b < 0) c128b = i; else c128c = i; }
                else if (s == 1) ibc = i;
            }
            iW1 = w16a; iW2 = w16b; ib1 = c128a; ib2 = c128b; iWc = c128c;
        }
    }

    const float* x  = (const float*)d_in[ix];
    const int*   ei = (const int*)d_in[iei];
    const int*   sa = (const int*)d_in[isa];
    const float* W1 = (const float*)d_in[iW1];
    const float* b1 = (const float*)d_in[ib1];
    const float* W2 = (const float*)d_in[iW2];
    const float* b2 = (const float*)d_in[ib2];
    const float* Wc = (const float*)d_in[iWc];
    const float* bc = (const float*)d_in[ibc];

    float* out  = (float*)d_out;
    float* yout = out;        // [N]
    float* hout = out + Nn;   // [N, 128]

    const int T = 256;
    const int gN      = (Nn + T - 1) / T;
    const int gNwarp  = (Nn + 7) / 8;
    const int gE16    = (Ee * 16 + T - 1) / T;     // 16 lanes per edge
    const int gE      = (Ee + T - 1) / T;
    const int gGemm   = (Nn + 127) / 128;          // 391

    static int smem_set = 0;
    if (!smem_set) {
        cudaFuncSetAttribute(k_gemmh, cudaFuncAttributeMaxDynamicSharedMemorySize,
                             2 * 128 * SK * (int)sizeof(__half));
        smem_set = 1;
    }
    const int SMEM = 2 * 128 * SK * (int)sizeof(__half);  // 69632 B

    // init + dtype detection
    k_init<<<gN, T>>>();
    k_detect<<<gE, T>>>(ei);

    // fp16 prep + edge weights
    k_xprep<<<gNwarp, T>>>(x);
    k_w2h<<<(2 * Hh * Hh + T - 1) / T, T>>>(W1, W2);
    k_edge<<<gE16, T>>>(ei, sa);

    // CSR build
    k_scan<<<1, 1024>>>();
    k_dinv<<<gN, T>>>();
    k_fill<<<gE, T>>>(ei);

    // layer 1
    k_gemmh<<<gGemm, T, SMEM>>>(0);
    k_aggc<<<gNwarp, T>>>(b1, nullptr, nullptr, nullptr, nullptr, 1);

    // layer 2 (+fused head)
    k_gemmh<<<gGemm, T, SMEM>>>(1);
    k_aggc<<<gNwarp, T>>>(b2, hout, Wc, bc, yout, 0);
}